// round 6
// baseline (speedup 1.0000x reference)
#include <cuda_runtime.h>
#include <math.h>
#include <stdint.h>

// Problem constants
#define Bb   4
#define Hh   16
#define TQn  2048
#define TKn  2048
#define Dk   64
#define Dv   64

#define BM       16      // q rows per block
#define BN       128     // k rows per K/V smem tile
#define THREADS  256
#define KSTRIDE  68      // padded float stride for K/V tile rows
#define QSTRIDE  68      // padded float stride for Q tile rows
#define SSTR     (TKn + 4)   // padded score-row stride
#define SCALE    0.125f  // 1/sqrt(64)

#define OUT_ELEMS  ((size_t)Bb * Hh * TQn * Dv)          // 8388608
#define ATTN_ELEMS ((size_t)Bb * Hh * TQn * (size_t)TKn) // 268435456

// smem floats: scores BM*SSTR + 2 kv buffers + q + sinv
#define SMEM_FLOATS (BM * SSTR + 2 * BN * KSTRIDE + BM * QSTRIDE + BM)
#define SMEM_BYTES  (SMEM_FLOATS * 4)

// ---- packed f32x2 helpers (sm_100+ PTX; ptxas never auto-fuses these) ----
__device__ __forceinline__ void fma2(unsigned long long& d,
                                     unsigned long long a,
                                     unsigned long long b) {
    asm("fma.rn.f32x2 %0, %1, %2, %0;" : "+l"(d) : "l"(a), "l"(b));
}
__device__ __forceinline__ void add2(unsigned long long& d, unsigned long long a) {
    asm("add.rn.f32x2 %0, %0, %1;" : "+l"(d) : "l"(a));
}
__device__ __forceinline__ unsigned long long pk2(float p) {
    unsigned long long r;
    asm("mov.b64 %0, {%1, %1};" : "=l"(r) : "f"(p));
    return r;
}
__device__ __forceinline__ float2 unpk2(unsigned long long v) {
    float2 r;
    asm("mov.b64 {%0, %1}, %2;" : "=f"(r.x), "=f"(r.y) : "l"(v));
    return r;
}

__global__ __launch_bounds__(THREADS, 1)
void sdpa_fused_kernel(const float* __restrict__ Q,
                       const float* __restrict__ K,
                       const float* __restrict__ V,
                       const int*   __restrict__ mask,
                       float* __restrict__ out,
                       float* __restrict__ attn)   // may be null
{
    extern __shared__ float smem[];
    float* s    = smem;                                   // [BM][SSTR]
    float* kvs  = smem + BM * SSTR;                       // 2 x [BN][KSTRIDE]
    float* qs   = kvs + 2 * BN * KSTRIDE;                 // [BM][QSTRIDE]
    float* sinv = qs + BM * QSTRIDE;                      // [BM]

    const int tid  = threadIdx.x;
    const int w    = tid >> 5;
    const int lane = tid & 31;

    // block decode: h innermost for mask L2 reuse across heads
    int bid = blockIdx.x;
    const int h  = bid % Hh;   bid /= Hh;
    const int qt = bid % (TQn / BM);
    const int b  = bid / (TQn / BM);
    const int q0 = qt * BM;
    const int bh = b * Hh + h;

    const float* Qp = Q + ((size_t)bh * TQn + q0) * Dk;
    const float* Kp = K + (size_t)bh * TKn * Dk;
    const float* Vp = V + (size_t)bh * TKn * Dv;
    const int*   Mp = mask + (size_t)b * TQn * TKn + (size_t)q0 * TKn;

    // global<->smem tile indexing (16 rows per 256-thread step)
    const int d4i = tid & 15;       // float4 index within 64-float row
    const int kr0 = tid >> 4;       // base row

    // ---- load Q tile (BM x 64) ----
    {
        float4 v = ((const float4*)(Qp + (size_t)kr0 * Dk))[d4i];
        ((float4*)(qs + kr0 * QSTRIDE))[d4i] = v;
    }

    // warp compute mapping
    const int rsub = lane >> 3;        // 0..3 (rows; broadcast group)
    const int csub = lane & 7;         // 0..7 (columns)

    // ================= Phase 1: scores = Q K^T * scale =================
    {
        const int strip = w >> 2;                 // 0..1: 64-col half of BN
        const int rg    = w & 3;
        const int r     = rg * 4 + rsub;          // 0..15
        const int cbase = strip * 64;
        const ulonglong2* q2 = (const ulonglong2*)(qs + r * QSTRIDE);

        int cur = 0;
        float4 pre[8];
        #pragma unroll
        for (int i = 0; i < 8; i++)
            pre[i] = ((const float4*)(Kp + (size_t)(kr0 + 16 * i) * Dk))[d4i];

        for (int kt = 0; kt < TKn / BN; kt++) {
            float* buf = kvs + cur * (BN * KSTRIDE);
            #pragma unroll
            for (int i = 0; i < 8; i++)
                ((float4*)(buf + (kr0 + 16 * i) * KSTRIDE))[d4i] = pre[i];
            __syncthreads();
            if (kt + 1 < TKn / BN) {
                const float* Kt = Kp + (size_t)(kt + 1) * BN * Dk;
                #pragma unroll
                for (int i = 0; i < 8; i++)
                    pre[i] = ((const float4*)(Kt + (size_t)(kr0 + 16 * i) * Dk))[d4i];
            }

            // conflict-free: lane column = cbase + csub + 8*j
            const float* kcol0 = buf + (cbase + csub) * KSTRIDE;
            unsigned long long acc2[8] = {0,0,0,0,0,0,0,0};
            #pragma unroll 4
            for (int d4 = 0; d4 < 16; d4++) {
                ulonglong2 qv = q2[d4];
                #pragma unroll
                for (int j = 0; j < 8; j++) {
                    ulonglong2 kv = ((const ulonglong2*)(kcol0 + (size_t)j * 8 * KSTRIDE))[d4];
                    fma2(acc2[j], qv.x, kv.x);
                    fma2(acc2[j], qv.y, kv.y);
                }
            }
            float* srow = s + r * SSTR + kt * BN + cbase + csub;
            #pragma unroll
            for (int j = 0; j < 8; j++) {
                float2 v = unpk2(acc2[j]);
                srow[8 * j] = (v.x + v.y) * SCALE;
            }
            cur ^= 1;
        }
    }
    __syncthreads();

    // ================= Phase 2: mask + softmax (rows 2w, 2w+1 per warp) ====
    {
        #pragma unroll
        for (int rr = 2 * w; rr <= 2 * w + 1; rr++) {
            float4* srow4 = (float4*)(s + rr * SSTR);
            const int4* mrow4 = (const int4*)(Mp + (size_t)rr * TKn);

            float m = -1e30f;
            #pragma unroll 4
            for (int i = lane; i < TKn / 4; i += 32) {
                float4 sv = srow4[i];
                int4   mv = mrow4[i];
                sv.x = mv.x ? sv.x : -1e30f;
                sv.y = mv.y ? sv.y : -1e30f;
                sv.z = mv.z ? sv.z : -1e30f;
                sv.w = mv.w ? sv.w : -1e30f;
                srow4[i] = sv;
                m = fmaxf(m, fmaxf(fmaxf(sv.x, sv.y), fmaxf(sv.z, sv.w)));
            }
            #pragma unroll
            for (int off = 16; off; off >>= 1)
                m = fmaxf(m, __shfl_xor_sync(0xffffffffu, m, off));

            float l = 0.f;
            #pragma unroll 4
            for (int i = lane; i < TKn / 4; i += 32) {
                float4 sv = srow4[i];
                sv.x = __expf(sv.x - m);
                sv.y = __expf(sv.y - m);
                sv.z = __expf(sv.z - m);
                sv.w = __expf(sv.w - m);
                srow4[i] = sv;
                l += sv.x + sv.y + sv.z + sv.w;
            }
            #pragma unroll
            for (int off = 16; off; off >>= 1)
                l += __shfl_xor_sync(0xffffffffu, l, off);

            float inv = (l > 0.f) ? (1.f / l) : 0.f;
            if (lane == 0) sinv[rr] = inv;

            if (attn) {
                float4* arow = (float4*)(attn + ((size_t)bh * TQn + q0 + rr) * TKn);
                #pragma unroll 4
                for (int i = lane; i < TKn / 4; i += 32) {
                    float4 e = srow4[i];
                    e.x *= inv; e.y *= inv; e.z *= inv; e.w *= inv;
                    __stcs(&arow[i], e);   // streaming: attn never re-read; keep L2 for mask/K/V
                }
            }
        }
    }
    __syncthreads();

    // ================= Phase 3: out = P V (normalize at the end) ==========
    {
        const int khalf = w >> 2;                 // which 64-k half of tile
        const int rg    = w & 3;
        const int r     = rg * 4 + rsub;
        // thread's output columns: csub*4..+3 and 32+csub*4..+3 (4 f32x2 pairs)
        unsigned long long acc2[4] = {0,0,0,0};
        const float* srow = s + r * SSTR;

        int cur = 0;
        float4 pre[8];
        #pragma unroll
        for (int i = 0; i < 8; i++)
            pre[i] = ((const float4*)(Vp + (size_t)(kr0 + 16 * i) * Dv))[d4i];

        for (int kt = 0; kt < TKn / BN; kt++) {
            float* buf = kvs + cur * (BN * KSTRIDE);
            #pragma unroll
            for (int i = 0; i < 8; i++)
                ((float4*)(buf + (kr0 + 16 * i) * KSTRIDE))[d4i] = pre[i];
            __syncthreads();
            if (kt + 1 < TKn / BN) {
                const float* Vt = Vp + (size_t)(kt + 1) * BN * Dv;
                #pragma unroll
                for (int i = 0; i < 8; i++)
                    pre[i] = ((const float4*)(Vt + (size_t)(kr0 + 16 * i) * Dv))[d4i];
            }

            const float* pbase = srow + kt * BN + khalf * 64;
            const float* vbase = buf + khalf * 64 * KSTRIDE;
            #pragma unroll 4
            for (int kk4 = 0; kk4 < 16; kk4++) {
                float4 p4 = ((const float4*)pbase)[kk4];
                #pragma unroll
                for (int u = 0; u < 4; u++) {
                    float p = (u == 0) ? p4.x : (u == 1) ? p4.y : (u == 2) ? p4.z : p4.w;
                    unsigned long long pp = pk2(p);
                    const float* vrow = vbase + (kk4 * 4 + u) * KSTRIDE;
                    ulonglong2 va = ((const ulonglong2*)vrow)[csub];        // cols csub*4..+3
                    ulonglong2 vb = ((const ulonglong2*)(vrow + 32))[csub]; // cols 32+csub*4..+3
                    fma2(acc2[0], pp, va.x);
                    fma2(acc2[1], pp, va.y);
                    fma2(acc2[2], pp, vb.x);
                    fma2(acc2[3], pp, vb.y);
                }
            }
            cur ^= 1;
        }

        // reduce khalf=1 warps into khalf=0 warps via qs scratch
        __syncthreads();
        if (khalf == 1) {
            unsigned long long* dst =
                (unsigned long long*)qs + ((size_t)(w - 4) * 32 + lane) * 4;
            #pragma unroll
            for (int t = 0; t < 4; t++) dst[t] = acc2[t];
        }
        __syncthreads();
        if (khalf == 0) {
            const unsigned long long* src =
                (const unsigned long long*)qs + ((size_t)w * 32 + lane) * 4;
            #pragma unroll
            for (int t = 0; t < 4; t++) add2(acc2[t], src[t]);
            float inv = sinv[r];
            float2 a0 = unpk2(acc2[0]);
            float2 a1 = unpk2(acc2[1]);
            float2 a2 = unpk2(acc2[2]);
            float2 a3 = unpk2(acc2[3]);
            float* orow = out + ((size_t)bh * TQn + q0 + r) * Dv;
            ((float4*)orow)[csub]     = make_float4(a0.x*inv, a0.y*inv, a1.x*inv, a1.y*inv);
            ((float4*)orow)[8 + csub] = make_float4(a2.x*inv, a2.y*inv, a3.x*inv, a3.y*inv);
        }
    }
}

extern "C" void kernel_launch(void* const* d_in, const int* in_sizes, int n_in,
                              void* d_out, int out_size)
{
    const float* Q    = (const float*)d_in[0];
    const float* K    = (const float*)d_in[1];
    const float* V    = (const float*)d_in[2];
    const int*   mask = (const int*)  d_in[3];

    float* out  = (float*)d_out;
    float* attn = ((size_t)out_size >= OUT_ELEMS + ATTN_ELEMS) ? out + OUT_ELEMS : nullptr;

    cudaFuncSetAttribute(sdpa_fused_kernel,
                         cudaFuncAttributeMaxDynamicSharedMemorySize, SMEM_BYTES);

    dim3 grid(Bb * Hh * (TQn / BM));
    sdpa_fused_kernel<<<grid, THREADS, SMEM_BYTES>>>(Q, K, V, mask, out, attn);
}

// round 11
// speedup vs baseline: 1.6995x; 1.6995x over previous
#include <cuda_runtime.h>
#include <math.h>
#include <stdint.h>

// Problem constants
#define Bb   4
#define Hh   16
#define TQn  2048
#define TKn  2048
#define Dk   64
#define Dv   64

#define BM       16      // q rows per block
#define BN       128     // k rows per K/V smem tile
#define THREADS  256
#define KSTRIDE  68      // padded float stride for K/V tile rows
#define QSTRIDE  68      // padded float stride for Q tile rows
#define SSTR     (TKn + 4)   // padded score-row stride
#define SCALE    0.125f  // 1/sqrt(64)

#define OUT_ELEMS  ((size_t)Bb * Hh * TQn * Dv)          // 8388608
#define ATTN_ELEMS ((size_t)Bb * Hh * TQn * (size_t)TKn) // 268435456

#define SMEM_FLOATS (BM * SSTR + 2 * BN * KSTRIDE + BM * QSTRIDE + BM)
#define SMEM_BYTES  (SMEM_FLOATS * 4)

// ---- tf32 helpers ----
__device__ __forceinline__ uint32_t f2tf(float x) {
    uint32_t r;
    asm("cvt.rna.tf32.f32 %0, %1;" : "=r"(r) : "f"(x));
    return r;
}
// D += A(16x8) * B(8x8), tf32 inputs, f32 accum
__device__ __forceinline__ void mma8(float c[4], const uint32_t a[4], const uint32_t b[2]) {
    asm("mma.sync.aligned.m16n8k8.row.col.f32.tf32.tf32.f32 "
        "{%0,%1,%2,%3},{%4,%5,%6,%7},{%8,%9},{%0,%1,%2,%3};"
        : "+f"(c[0]), "+f"(c[1]), "+f"(c[2]), "+f"(c[3])
        : "r"(a[0]), "r"(a[1]), "r"(a[2]), "r"(a[3]), "r"(b[0]), "r"(b[1]));
}

__global__ __launch_bounds__(THREADS, 1)
void sdpa_fused_kernel(const float* __restrict__ Q,
                       const float* __restrict__ K,
                       const float* __restrict__ V,
                       const int*   __restrict__ mask,
                       float* __restrict__ out,
                       float* __restrict__ attn)   // may be null
{
    extern __shared__ float smem[];
    float* s    = smem;                                   // [BM][SSTR]
    float* kvs  = smem + BM * SSTR;                       // 2 x [BN][KSTRIDE]
    float* qs   = kvs + 2 * BN * KSTRIDE;                 // [BM][QSTRIDE]
    float* sinv = qs + BM * QSTRIDE;                      // [BM]

    const int tid  = threadIdx.x;
    const int w    = tid >> 5;
    const int lane = tid & 31;

    // block decode: h innermost for mask L2 reuse across heads
    int bid = blockIdx.x;
    const int h  = bid % Hh;   bid /= Hh;
    const int qt = bid % (TQn / BM);
    const int b  = bid / (TQn / BM);
    const int q0 = qt * BM;
    const int bhid = b * Hh + h;

    const float* Qp = Q + ((size_t)bhid * TQn + q0) * Dk;
    const float* Kp = K + (size_t)bhid * TKn * Dk;
    const float* Vp = V + (size_t)bhid * TKn * Dv;
    const int*   Mp = mask + (size_t)b * TQn * TKn + (size_t)q0 * TKn;

    // global<->smem tile indexing (16 rows per 256-thread step)
    const int d4i = tid & 15;       // float4 index within 64-float row
    const int kr0 = tid >> 4;       // base row

    // ---- load Q tile (BM x 64) ----
    {
        float4 v = ((const float4*)(Qp + (size_t)kr0 * Dk))[d4i];
        ((float4*)(qs + kr0 * QSTRIDE))[d4i] = v;
    }
    __syncthreads();   // qs visible before fragment precompute

    const int gid = lane >> 2;     // 0..7  (fragment row group)
    const int tig = lane & 3;      // 0..3  (thread in group)

    // ================= Phase 1: scores = Q K^T * scale (tf32 MMA) ==========
    {
        // Precompute A (Q) fragments hi/lo for all 8 d-chunks.
        uint32_t Ahi[8][4], Alo[8][4];
        #pragma unroll
        for (int ch = 0; ch < 8; ch++) {
            float av[4];
            av[0] = qs[gid * QSTRIDE + ch * 8 + tig];
            av[1] = qs[(gid + 8) * QSTRIDE + ch * 8 + tig];
            av[2] = qs[gid * QSTRIDE + ch * 8 + tig + 4];
            av[3] = qs[(gid + 8) * QSTRIDE + ch * 8 + tig + 4];
            #pragma unroll
            for (int i = 0; i < 4; i++) {
                Ahi[ch][i] = f2tf(av[i]);
                Alo[ch][i] = f2tf(av[i] - __uint_as_float(Ahi[ch][i]));
            }
        }

        int cur = 0;
        float4 pre[8];
        #pragma unroll
        for (int i = 0; i < 8; i++)
            pre[i] = ((const float4*)(Kp + (size_t)(kr0 + 16 * i) * Dk))[d4i];

        for (int kt = 0; kt < TKn / BN; kt++) {
            float* buf = kvs + cur * (BN * KSTRIDE);
            #pragma unroll
            for (int i = 0; i < 8; i++)
                ((float4*)(buf + (kr0 + 16 * i) * KSTRIDE))[d4i] = pre[i];
            __syncthreads();
            if (kt + 1 < TKn / BN) {
                const float* Kt = Kp + (size_t)(kt + 1) * BN * Dk;
                #pragma unroll
                for (int i = 0; i < 8; i++)
                    pre[i] = ((const float4*)(Kt + (size_t)(kr0 + 16 * i) * Dk))[d4i];
            }

            // warp w covers cols [w*16, w*16+16) of this 128-col tile
            #pragma unroll
            for (int t = 0; t < 2; t++) {
                const int n0 = w * 16 + t * 8;
                float c[4] = {0.f, 0.f, 0.f, 0.f};
                #pragma unroll
                for (int ch = 0; ch < 8; ch++) {
                    const float* bp = buf + (n0 + gid) * KSTRIDE + ch * 8 + tig;
                    float b0 = bp[0], b1 = bp[4];
                    uint32_t bh2[2] = { f2tf(b0), f2tf(b1) };
                    uint32_t bl2[2] = { f2tf(b0 - __uint_as_float(bh2[0])),
                                        f2tf(b1 - __uint_as_float(bh2[1])) };
                    mma8(c, Ahi[ch], bh2);
                    mma8(c, Ahi[ch], bl2);
                    mma8(c, Alo[ch], bh2);
                }
                float* p0 = s + gid * SSTR + kt * BN + n0 + 2 * tig;
                float* p1 = s + (gid + 8) * SSTR + kt * BN + n0 + 2 * tig;
                ((float2*)p0)[0] = make_float2(c[0] * SCALE, c[1] * SCALE);
                ((float2*)p1)[0] = make_float2(c[2] * SCALE, c[3] * SCALE);
            }
            cur ^= 1;
        }
    }
    __syncthreads();

    // ================= Phase 2: mask + softmax (rows 2w, 2w+1 per warp) ====
    {
        #pragma unroll
        for (int rr = 2 * w; rr <= 2 * w + 1; rr++) {
            float4* srow4 = (float4*)(s + rr * SSTR);
            const int4* mrow4 = (const int4*)(Mp + (size_t)rr * TKn);

            float m = -1e30f;
            #pragma unroll 4
            for (int i = lane; i < TKn / 4; i += 32) {
                float4 sv = srow4[i];
                int4   mv = mrow4[i];
                sv.x = mv.x ? sv.x : -1e30f;
                sv.y = mv.y ? sv.y : -1e30f;
                sv.z = mv.z ? sv.z : -1e30f;
                sv.w = mv.w ? sv.w : -1e30f;
                srow4[i] = sv;
                m = fmaxf(m, fmaxf(fmaxf(sv.x, sv.y), fmaxf(sv.z, sv.w)));
            }
            #pragma unroll
            for (int off = 16; off; off >>= 1)
                m = fmaxf(m, __shfl_xor_sync(0xffffffffu, m, off));

            float l = 0.f;
            #pragma unroll 4
            for (int i = lane; i < TKn / 4; i += 32) {
                float4 sv = srow4[i];
                sv.x = __expf(sv.x - m);
                sv.y = __expf(sv.y - m);
                sv.z = __expf(sv.z - m);
                sv.w = __expf(sv.w - m);
                srow4[i] = sv;
                l += sv.x + sv.y + sv.z + sv.w;
            }
            #pragma unroll
            for (int off = 16; off; off >>= 1)
                l += __shfl_xor_sync(0xffffffffu, l, off);

            float inv = (l > 0.f) ? (1.f / l) : 0.f;
            if (lane == 0) sinv[rr] = inv;

            if (attn) {
                float4* arow = (float4*)(attn + ((size_t)bhid * TQn + q0 + rr) * TKn);
                #pragma unroll 4
                for (int i = lane; i < TKn / 4; i += 32) {
                    float4 e = srow4[i];
                    e.x *= inv; e.y *= inv; e.z *= inv; e.w *= inv;
                    __stcs(&arow[i], e);   // streaming: attn never re-read
                }
            }
        }
    }
    __syncthreads();

    // ================= Phase 3: out = P V (tf32 MMA, normalize at end) =====
    {
        const int n0 = w * 8;          // this warp's 8 dv columns
        float c[4] = {0.f, 0.f, 0.f, 0.f};

        int cur = 0;
        float4 pre[8];
        #pragma unroll
        for (int i = 0; i < 8; i++)
            pre[i] = ((const float4*)(Vp + (size_t)(kr0 + 16 * i) * Dv))[d4i];

        for (int kt = 0; kt < TKn / BN; kt++) {
            float* buf = kvs + cur * (BN * KSTRIDE);
            #pragma unroll
            for (int i = 0; i < 8; i++)
                ((float4*)(buf + (kr0 + 16 * i) * KSTRIDE))[d4i] = pre[i];
            __syncthreads();
            if (kt + 1 < TKn / BN) {
                const float* Vt = Vp + (size_t)(kt + 1) * BN * Dv;
                #pragma unroll
                for (int i = 0; i < 8; i++)
                    pre[i] = ((const float4*)(Vt + (size_t)(kr0 + 16 * i) * Dv))[d4i];
            }

            const float* srow0 = s + gid * SSTR + kt * BN;
            const float* srow1 = s + (gid + 8) * SSTR + kt * BN;
            #pragma unroll
            for (int ch = 0; ch < 16; ch++) {
                const int k0 = ch * 8;
                float a0 = srow0[k0 + tig];
                float a1 = srow1[k0 + tig];
                float a2 = srow0[k0 + tig + 4];
                float a3 = srow1[k0 + tig + 4];
                uint32_t ah[4] = { f2tf(a0), f2tf(a1), f2tf(a2), f2tf(a3) };
                uint32_t al[4] = { f2tf(a0 - __uint_as_float(ah[0])),
                                   f2tf(a1 - __uint_as_float(ah[1])),
                                   f2tf(a2 - __uint_as_float(ah[2])),
                                   f2tf(a3 - __uint_as_float(ah[3])) };
                const float* vp = buf + (k0 + tig) * KSTRIDE + n0 + gid;
                float b0 = vp[0];
                float b1 = vp[4 * KSTRIDE];
                uint32_t bh2[2] = { f2tf(b0), f2tf(b1) };
                uint32_t bl2[2] = { f2tf(b0 - __uint_as_float(bh2[0])),
                                    f2tf(b1 - __uint_as_float(bh2[1])) };
                mma8(c, ah, bh2);
                mma8(c, ah, bl2);
                mma8(c, al, bh2);
            }
            cur ^= 1;
        }

        // epilogue: normalize rows and store (each warp owns its dv slice)
        float inv0 = sinv[gid];
        float inv1 = sinv[gid + 8];
        float* o0 = out + ((size_t)bhid * TQn + q0 + gid) * Dv + n0 + 2 * tig;
        float* o1 = out + ((size_t)bhid * TQn + q0 + gid + 8) * Dv + n0 + 2 * tig;
        ((float2*)o0)[0] = make_float2(c[0] * inv0, c[1] * inv0);
        ((float2*)o1)[0] = make_float2(c[2] * inv1, c[3] * inv1);
    }
}

extern "C" void kernel_launch(void* const* d_in, const int* in_sizes, int n_in,
                              void* d_out, int out_size)
{
    const float* Q    = (const float*)d_in[0];
    const float* K    = (const float*)d_in[1];
    const float* V    = (const float*)d_in[2];
    const int*   mask = (const int*)  d_in[3];

    float* out  = (float*)d_out;
    float* attn = ((size_t)out_size >= OUT_ELEMS + ATTN_ELEMS) ? out + OUT_ELEMS : nullptr;

    cudaFuncSetAttribute(sdpa_fused_kernel,
                         cudaFuncAttributeMaxDynamicSharedMemorySize, SMEM_BYTES);

    dim3 grid(Bb * Hh * (TQn / BM));
    sdpa_fused_kernel<<<grid, THREADS, SMEM_BYTES>>>(Q, K, V, mask, out, attn);
}

// round 15
// speedup vs baseline: 1.8947x; 1.1149x over previous
#include <cuda_runtime.h>
#include <math.h>
#include <stdint.h>

// Problem constants
#define Bb   4
#define Hh   16
#define TQn  2048
#define TKn  2048
#define Dk   64
#define Dv   64

#define BM       16      // q rows per block
#define BN       128     // k rows per K/V smem tile
#define THREADS  256
#define KSTRIDE  68      // padded float stride for K/V tile rows
#define QSTRIDE  68      // padded float stride for Q tile rows
#define SSTR     (TKn + 4)   // padded score-row stride
#define PSTR     132         // padded plo tile row stride
#define SCALE    0.125f  // 1/sqrt(64)

#define OUT_ELEMS  ((size_t)Bb * Hh * TQn * Dv)          // 8388608
#define ATTN_ELEMS ((size_t)Bb * Hh * TQn * (size_t)TKn) // 268435456

#define SMEM_FLOATS (BM * SSTR + 2 * BN * KSTRIDE + BM * QSTRIDE + BM + 2 * BM * PSTR)
#define SMEM_BYTES  (SMEM_FLOATS * 4)

// ---- tf32 helpers ----
__device__ __forceinline__ uint32_t f2tf(float x) {
    uint32_t r;
    asm("cvt.rna.tf32.f32 %0, %1;" : "=r"(r) : "f"(x));
    return r;
}
// D += A(16x8) * B(8x8), tf32 inputs, f32 accum
__device__ __forceinline__ void mma8(float c[4], const uint32_t a[4], const uint32_t b[2]) {
    asm("mma.sync.aligned.m16n8k8.row.col.f32.tf32.tf32.f32 "
        "{%0,%1,%2,%3},{%4,%5,%6,%7},{%8,%9},{%0,%1,%2,%3};"
        : "+f"(c[0]), "+f"(c[1]), "+f"(c[2]), "+f"(c[3])
        : "r"(a[0]), "r"(a[1]), "r"(a[2]), "r"(a[3]), "r"(b[0]), "r"(b[1]));
}

__global__ __launch_bounds__(THREADS, 1)
void sdpa_fused_kernel(const float* __restrict__ Q,
                       const float* __restrict__ K,
                       const float* __restrict__ V,
                       const int*   __restrict__ mask,
                       float* __restrict__ out,
                       float* __restrict__ attn)   // may be null
{
    extern __shared__ float smem[];
    float* s    = smem;                                   // [BM][SSTR]
    float* kvs  = smem + BM * SSTR;                       // 2 x [BN][KSTRIDE]
    float* qs   = kvs + 2 * BN * KSTRIDE;                 // [BM][QSTRIDE]
    float* sinv = qs + BM * QSTRIDE;                      // [BM]
    float* plo  = sinv + BM;                              // 2 x [BM][PSTR]

    const int tid  = threadIdx.x;
    const int w    = tid >> 5;
    const int lane = tid & 31;

    // block decode: h innermost for mask L2 reuse across heads
    int bid = blockIdx.x;
    const int h  = bid % Hh;   bid /= Hh;
    const int qt = bid % (TQn / BM);
    const int b  = bid / (TQn / BM);
    const int q0 = qt * BM;
    const int bhid = b * Hh + h;

    const float* Qp = Q + ((size_t)bhid * TQn + q0) * Dk;
    const float* Kp = K + (size_t)bhid * TKn * Dk;
    const float* Vp = V + (size_t)bhid * TKn * Dv;
    const int*   Mp = mask + (size_t)b * TQn * TKn + (size_t)q0 * TKn;

    // global<->smem tile indexing (16 rows per 256-thread step)
    const int d4i = tid & 15;       // float4 index within 64-float row
    const int kr0 = tid >> 4;       // base row

    // ---- load Q tile (BM x 64) ----
    {
        float4 v = ((const float4*)(Qp + (size_t)kr0 * Dk))[d4i];
        ((float4*)(qs + kr0 * QSTRIDE))[d4i] = v;
    }
    __syncthreads();   // qs visible before fragment precompute

    const int gid = lane >> 2;     // 0..7  (fragment row group)
    const int tig = lane & 3;      // 0..3  (thread in group)

    // ================= Phase 1: scores = Q K^T * scale (tf32 MMA) ==========
    {
        // Precompute A (Q) fragments hi/lo for all 8 d-chunks.
        uint32_t Ahi[8][4], Alo[8][4];
        #pragma unroll
        for (int ch = 0; ch < 8; ch++) {
            float av[4];
            av[0] = qs[gid * QSTRIDE + ch * 8 + tig];
            av[1] = qs[(gid + 8) * QSTRIDE + ch * 8 + tig];
            av[2] = qs[gid * QSTRIDE + ch * 8 + tig + 4];
            av[3] = qs[(gid + 8) * QSTRIDE + ch * 8 + tig + 4];
            #pragma unroll
            for (int i = 0; i < 4; i++) {
                Ahi[ch][i] = f2tf(av[i]);
                Alo[ch][i] = f2tf(av[i] - __uint_as_float(Ahi[ch][i]));
            }
        }

        int cur = 0;
        float4 pre[8];
        #pragma unroll
        for (int i = 0; i < 8; i++)
            pre[i] = ((const float4*)(Kp + (size_t)(kr0 + 16 * i) * Dk))[d4i];

        for (int kt = 0; kt < TKn / BN; kt++) {
            float* buf = kvs + cur * (BN * KSTRIDE);
            #pragma unroll
            for (int i = 0; i < 8; i++)
                ((float4*)(buf + (kr0 + 16 * i) * KSTRIDE))[d4i] = pre[i];
            __syncthreads();
            if (kt + 1 < TKn / BN) {
                const float* Kt = Kp + (size_t)(kt + 1) * BN * Dk;
                #pragma unroll
                for (int i = 0; i < 8; i++)
                    pre[i] = ((const float4*)(Kt + (size_t)(kr0 + 16 * i) * Dk))[d4i];
            }

            // warp w covers cols [w*16, w*16+16) of this 128-col tile
            #pragma unroll
            for (int t = 0; t < 2; t++) {
                const int n0 = w * 16 + t * 8;
                // independent accumulators per pass -> 3 MMA chains
                float chh[4] = {0.f, 0.f, 0.f, 0.f};
                float chl[4] = {0.f, 0.f, 0.f, 0.f};
                float clh[4] = {0.f, 0.f, 0.f, 0.f};
                #pragma unroll
                for (int ch = 0; ch < 8; ch++) {
                    const float* bp = buf + (n0 + gid) * KSTRIDE + ch * 8 + tig;
                    float b0 = bp[0], b1 = bp[4];
                    uint32_t bh2[2] = { f2tf(b0), f2tf(b1) };
                    uint32_t bl2[2] = { f2tf(b0 - __uint_as_float(bh2[0])),
                                        f2tf(b1 - __uint_as_float(bh2[1])) };
                    mma8(chh, Ahi[ch], bh2);
                    mma8(chl, Ahi[ch], bl2);
                    mma8(clh, Alo[ch], bh2);
                }
                float* p0 = s + gid * SSTR + kt * BN + n0 + 2 * tig;
                float* p1 = s + (gid + 8) * SSTR + kt * BN + n0 + 2 * tig;
                ((float2*)p0)[0] = make_float2((chh[0] + chl[0] + clh[0]) * SCALE,
                                               (chh[1] + chl[1] + clh[1]) * SCALE);
                ((float2*)p1)[0] = make_float2((chh[2] + chl[2] + clh[2]) * SCALE,
                                               (chh[3] + chl[3] + clh[3]) * SCALE);
            }
            cur ^= 1;
        }
    }
    __syncthreads();

    // ================= Phase 2: mask + softmax (rows 2w, 2w+1 per warp) ====
    {
        #pragma unroll
        for (int rr = 2 * w; rr <= 2 * w + 1; rr++) {
            float4* srow4 = (float4*)(s + rr * SSTR);
            const int4* mrow4 = (const int4*)(Mp + (size_t)rr * TKn);

            float m = -1e30f;
            #pragma unroll 4
            for (int i = lane; i < TKn / 4; i += 32) {
                float4 sv = srow4[i];
                int4   mv = mrow4[i];
                sv.x = mv.x ? sv.x : -1e30f;
                sv.y = mv.y ? sv.y : -1e30f;
                sv.z = mv.z ? sv.z : -1e30f;
                sv.w = mv.w ? sv.w : -1e30f;
                srow4[i] = sv;
                m = fmaxf(m, fmaxf(fmaxf(sv.x, sv.y), fmaxf(sv.z, sv.w)));
            }
            #pragma unroll
            for (int off = 16; off; off >>= 1)
                m = fmaxf(m, __shfl_xor_sync(0xffffffffu, m, off));

            float l = 0.f;
            #pragma unroll 4
            for (int i = lane; i < TKn / 4; i += 32) {
                float4 sv = srow4[i];
                sv.x = __expf(sv.x - m);
                sv.y = __expf(sv.y - m);
                sv.z = __expf(sv.z - m);
                sv.w = __expf(sv.w - m);
                srow4[i] = sv;
                l += sv.x + sv.y + sv.z + sv.w;
            }
            #pragma unroll
            for (int off = 16; off; off >>= 1)
                l += __shfl_xor_sync(0xffffffffu, l, off);

            float inv = (l > 0.f) ? (1.f / l) : 0.f;
            if (lane == 0) sinv[rr] = inv;

            if (attn) {
                float4* arow = (float4*)(attn + ((size_t)bhid * TQn + q0 + rr) * TKn);
                #pragma unroll 4
                for (int i = lane; i < TKn / 4; i += 32) {
                    float4 e = srow4[i];
                    e.x *= inv; e.y *= inv; e.z *= inv; e.w *= inv;
                    __stcs(&arow[i], e);   // streaming: attn never re-read
                }
            }
        }
    }
    __syncthreads();

    // ================= Phase 3: out = P V (tf32 MMA, normalize at end) =====
    {
        const int n0 = w * 8;          // this warp's 8 dv columns
        // independent accumulators per pass -> 3 MMA chains across all tiles
        float chh[4] = {0.f, 0.f, 0.f, 0.f};
        float chl[4] = {0.f, 0.f, 0.f, 0.f};
        float clh[4] = {0.f, 0.f, 0.f, 0.f};

        int cur = 0;
        float4 pre[8];
        #pragma unroll
        for (int i = 0; i < 8; i++)
            pre[i] = ((const float4*)(Vp + (size_t)(kr0 + 16 * i) * Dv))[d4i];

        for (int kt = 0; kt < TKn / BN; kt++) {
            float* buf     = kvs + cur * (BN * KSTRIDE);
            float* plo_buf = plo + cur * (BM * PSTR);
            // stage V tile
            #pragma unroll
            for (int i = 0; i < 8; i++)
                ((float4*)(buf + (kr0 + 16 * i) * KSTRIDE))[d4i] = pre[i];

            // cooperatively convert P tile kt ONCE: hi in place, lo -> plo_buf
            {
                #pragma unroll
                for (int q = 0; q < 2; q++) {
                    int idx = tid * 2 + q;        // 0..511 float4s
                    int row = idx >> 5;           // 0..15
                    int c4  = idx & 31;           // float4 col in tile
                    float4 p = ((float4*)(s + row * SSTR + kt * BN))[c4];
                    float4 hi, lo;
                    hi.x = __uint_as_float(f2tf(p.x)); lo.x = __uint_as_float(f2tf(p.x - hi.x));
                    hi.y = __uint_as_float(f2tf(p.y)); lo.y = __uint_as_float(f2tf(p.y - hi.y));
                    hi.z = __uint_as_float(f2tf(p.z)); lo.z = __uint_as_float(f2tf(p.z - hi.z));
                    hi.w = __uint_as_float(f2tf(p.w)); lo.w = __uint_as_float(f2tf(p.w - hi.w));
                    ((float4*)(s + row * SSTR + kt * BN))[c4] = hi;
                    ((float4*)(plo_buf + row * PSTR))[c4] = lo;
                }
            }
            __syncthreads();
            if (kt + 1 < TKn / BN) {
                const float* Vt = Vp + (size_t)(kt + 1) * BN * Dv;
                #pragma unroll
                for (int i = 0; i < 8; i++)
                    pre[i] = ((const float4*)(Vt + (size_t)(kr0 + 16 * i) * Dv))[d4i];
            }

            const float* srow0 = s + gid * SSTR + kt * BN;
            const float* srow1 = s + (gid + 8) * SSTR + kt * BN;
            const float* lrow0 = plo_buf + gid * PSTR;
            const float* lrow1 = plo_buf + (gid + 8) * PSTR;
            #pragma unroll
            for (int ch = 0; ch < 16; ch++) {
                const int k0 = ch * 8;
                uint32_t ah[4] = { __float_as_uint(srow0[k0 + tig]),
                                   __float_as_uint(srow1[k0 + tig]),
                                   __float_as_uint(srow0[k0 + tig + 4]),
                                   __float_as_uint(srow1[k0 + tig + 4]) };
                uint32_t al[4] = { __float_as_uint(lrow0[k0 + tig]),
                                   __float_as_uint(lrow1[k0 + tig]),
                                   __float_as_uint(lrow0[k0 + tig + 4]),
                                   __float_as_uint(lrow1[k0 + tig + 4]) };
                const float* vp = buf + (k0 + tig) * KSTRIDE + n0 + gid;
                float b0 = vp[0];
                float b1 = vp[4 * KSTRIDE];
                uint32_t bh2[2] = { f2tf(b0), f2tf(b1) };
                uint32_t bl2[2] = { f2tf(b0 - __uint_as_float(bh2[0])),
                                    f2tf(b1 - __uint_as_float(bh2[1])) };
                mma8(chh, ah, bh2);
                mma8(chl, ah, bl2);
                mma8(clh, al, bh2);
            }
            cur ^= 1;
        }

        // epilogue: combine passes, normalize rows and store
        float inv0 = sinv[gid];
        float inv1 = sinv[gid + 8];
        float c0 = chh[0] + chl[0] + clh[0];
        float c1 = chh[1] + chl[1] + clh[1];
        float c2 = chh[2] + chl[2] + clh[2];
        float c3 = chh[3] + chl[3] + clh[3];
        float* o0 = out + ((size_t)bhid * TQn + q0 + gid) * Dv + n0 + 2 * tig;
        float* o1 = out + ((size_t)bhid * TQn + q0 + gid + 8) * Dv + n0 + 2 * tig;
        ((float2*)o0)[0] = make_float2(c0 * inv0, c1 * inv0);
        ((float2*)o1)[0] = make_float2(c2 * inv1, c3 * inv1);
    }
}

extern "C" void kernel_launch(void* const* d_in, const int* in_sizes, int n_in,
                              void* d_out, int out_size)
{
    const float* Q    = (const float*)d_in[0];
    const float* K    = (const float*)d_in[1];
    const float* V    = (const float*)d_in[2];
    const int*   mask = (const int*)  d_in[3];

    float* out  = (float*)d_out;
    float* attn = ((size_t)out_size >= OUT_ELEMS + ATTN_ELEMS) ? out + OUT_ELEMS : nullptr;

    cudaFuncSetAttribute(sdpa_fused_kernel,
                         cudaFuncAttributeMaxDynamicSharedMemorySize, SMEM_BYTES);

    dim3 grid(Bb * Hh * (TQn / BM));
    sdpa_fused_kernel<<<grid, THREADS, SMEM_BYTES>>>(Q, K, V, mask, out, attn);
}